// round 1
// baseline (speedup 1.0000x reference)
#include <cuda_runtime.h>
#include <math.h>

#define NIMG 8
#define CH 3
#define HH 512
#define WW 512
#define GMIX 5
#define MF 3
#define HY 256
#define WY 256

// 6.3 MB scratch for downsampled y
__device__ float g_y[NIMG * CH * HY * WY];

struct Params {
    float Sinv[GMIX][6];      // symmetric 3x3: s00,s01,s02,s11,s12,s22
    float halflogdet[GMIX];
    float logpi[GMIX];
    float mu[GMIX][CH];
    float c[GMIX][MF];
    float rL[GMIX][MF];       // 1/sL
    float rR[GMIX][MF];       // 1/sR
    float g7[7];              // normalized gaussian taps
};
__device__ Params g_P;

__device__ __forceinline__ double softplus_d(double x) {
    if (x > 30.0) return x;
    return log1p(exp(x));
}

__global__ void precompute_kernel(const float* __restrict__ mu,
                                  const float* __restrict__ L_raw,
                                  const float* __restrict__ pi,
                                  const float* __restrict__ mf_c,
                                  const float* __restrict__ mf_sL,
                                  const float* __restrict__ mf_sR) {
    if (threadIdx.x != 0 || blockIdx.x != 0) return;

    // gaussian taps (SIGMA=0.9)
    {
        double gs[7], s = 0.0;
        for (int r = -3; r <= 3; r++) { gs[r + 3] = exp(-(double)(r * r) / (2.0 * 0.81)); s += gs[r + 3]; }
        for (int i = 0; i < 7; i++) g_P.g7[i] = (float)(gs[i] / s);
    }
    // log_softmax(pi)
    {
        double mx = -1e30;
        for (int g = 0; g < GMIX; g++) mx = fmax(mx, (double)pi[g]);
        double s = 0.0;
        for (int g = 0; g < GMIX; g++) s += exp((double)pi[g] - mx);
        double lse = mx + log(s);
        for (int g = 0; g < GMIX; g++) g_P.logpi[g] = (float)((double)pi[g] - lse);
    }
    for (int g = 0; g < GMIX; g++) {
        for (int i = 0; i < CH; i++) g_P.mu[g][i] = mu[g * CH + i];
        for (int m = 0; m < MF; m++) {
            g_P.c[g][m]  = mf_c[g * MF + m];
            double sL = softplus_d((double)mf_sL[g * MF + m]) + 1e-12;
            double sR = softplus_d((double)mf_sR[g * MF + m]) + 1e-12;
            g_P.rL[g][m] = (float)(1.0 / sL);
            g_P.rR[g][m] = (float)(1.0 / sR);
        }
        // build L (tril, transformed diagonal)
        double L[3][3];
        for (int i = 0; i < 3; i++)
            for (int j = 0; j < 3; j++) {
                double v = (double)L_raw[(g * 3 + i) * 3 + j];
                L[i][j] = (j < i) ? v : 0.0;
            }
        for (int i = 0; i < 3; i++) {
            double d = softplus_d((double)L_raw[(g * 3 + i) * 3 + i]) + 1e-4;  // MIN_DIAG
            d = softplus_d(d) + 1e-4;                                          // SIG_EPS
            L[i][i] = d;
        }
        // Sigma = L L^T + SIG_EPS I
        double Sg[3][3];
        for (int i = 0; i < 3; i++)
            for (int j = 0; j < 3; j++) {
                double acc = 0.0;
                for (int k = 0; k < 3; k++) acc += L[i][k] * L[j][k];
                Sg[i][j] = acc + (i == j ? 1e-4 : 0.0);
            }
        double det = Sg[0][0] * (Sg[1][1] * Sg[2][2] - Sg[1][2] * Sg[2][1])
                   - Sg[0][1] * (Sg[1][0] * Sg[2][2] - Sg[1][2] * Sg[2][0])
                   + Sg[0][2] * (Sg[1][0] * Sg[2][1] - Sg[1][1] * Sg[2][0]);
        g_P.halflogdet[g] = (float)(0.5 * log(det));
        // A = Sigma + JITTER I ; Sinv = A^{-1} (pinv of SPD = inverse)
        double A[3][3];
        for (int i = 0; i < 3; i++)
            for (int j = 0; j < 3; j++) A[i][j] = Sg[i][j] + (i == j ? 1e-3 : 0.0);
        double dA = A[0][0] * (A[1][1] * A[2][2] - A[1][2] * A[2][1])
                  - A[0][1] * (A[1][0] * A[2][2] - A[1][2] * A[2][0])
                  + A[0][2] * (A[1][0] * A[2][1] - A[1][1] * A[2][0]);
        double i00 =  (A[1][1] * A[2][2] - A[1][2] * A[2][1]) / dA;
        double i01 = -(A[0][1] * A[2][2] - A[0][2] * A[2][1]) / dA;
        double i02 =  (A[0][1] * A[1][2] - A[0][2] * A[1][1]) / dA;
        double i11 =  (A[0][0] * A[2][2] - A[0][2] * A[2][0]) / dA;
        double i12 = -(A[0][0] * A[1][2] - A[0][2] * A[1][0]) / dA;
        double i22 =  (A[0][0] * A[1][1] - A[0][1] * A[1][0]) / dA;
        g_P.Sinv[g][0] = (float)i00;
        g_P.Sinv[g][1] = (float)i01;
        g_P.Sinv[g][2] = (float)i02;
        g_P.Sinv[g][3] = (float)i11;
        g_P.Sinv[g][4] = (float)i12;
        g_P.Sinv[g][5] = (float)i22;
    }
}

// ---------------------------------------------------------------------------
// Kernel 1: separable 7x7 gaussian blur, reflect pad, stride 2.
// Tile: 32x8 outputs per block. Input tile 21 rows x 69 cols.
// ---------------------------------------------------------------------------
__global__ void __launch_bounds__(256) down_kernel(const float* __restrict__ x) {
    __shared__ float xs[21][69];
    __shared__ float tmp[21][32];
    __shared__ float gw[7];

    int tx = threadIdx.x & 31;
    int ty = threadIdx.x >> 5;
    int j0 = blockIdx.x * 32;
    int i0 = blockIdx.y * 8;
    int zc = blockIdx.z;  // n*CH + c
    const float* xin = x + (size_t)zc * HH * WW;

    if (threadIdx.x < 7) gw[threadIdx.x] = g_P.g7[threadIdx.x];

    for (int idx = threadIdx.x; idx < 21 * 69; idx += 256) {
        int rr = idx / 69, cc = idx - rr * 69;
        int r = 2 * i0 - 3 + rr;
        int c = 2 * j0 - 3 + cc;
        r = (r < 0) ? -r : (r >= HH ? 2 * HH - 2 - r : r);
        c = (c < 0) ? -c : (c >= WW ? 2 * WW - 2 - c : c);
        xs[rr][cc] = xin[r * WW + c];
    }
    __syncthreads();

    // horizontal pass (stride-2)
    for (int r = ty; r < 21; r += 8) {
        float acc = 0.f;
#pragma unroll
        for (int b = 0; b < 7; b++) acc += gw[b] * xs[r][2 * tx + b];
        tmp[r][tx] = acc;
    }
    __syncthreads();

    // vertical pass (stride-2)
    float acc = 0.f;
#pragma unroll
    for (int a = 0; a < 7; a++) acc += gw[a] * tmp[2 * ty + a][tx];
    g_y[((size_t)zc * HY + (i0 + ty)) * WY + (j0 + tx)] = acc;
}

// ---------------------------------------------------------------------------
// Kernel 2: fused upsample + GMM responsibilities + fuzzy membership.
// One block = 128 consecutive pixels of one row. Output staged in smem for
// fully-coalesced float stores.
// ---------------------------------------------------------------------------
__global__ void __launch_bounds__(128) main_kernel(float* __restrict__ out) {
    __shared__ float ys[CH][4][68];
    __shared__ Params P;
    __shared__ float so[128 * GMIX * MF];

    int tx = threadIdx.x;
    int b = blockIdx.x;
    int qb = b & 3;
    int p  = (b >> 2) & 511;
    int n  = b >> 11;
    int q0 = qb * 128;

    // params -> smem
    {
        const float* src = (const float*)&g_P;
        float* dst = (float*)&P;
        const int nP = (int)(sizeof(Params) / 4);
        for (int i = tx; i < nP; i += 128) dst[i] = src[i];
    }

    // stage needed y rows (zero-filled outside range)
    int odd   = p & 1;
    int m0    = odd ? (p - 3) / 2 : p / 2 - 1;
    int nrows = 3 + odd;
    const int ncol = 67;
    int n0 = q0 / 2 - 1;
    for (int idx = tx; idx < CH * 4 * ncol; idx += 128) {
        int c   = idx / (4 * ncol);
        int rem = idx - c * 4 * ncol;
        int r   = rem / ncol;
        int col = rem - r * ncol;
        float v = 0.f;
        int gm = m0 + r, gn = n0 + col;
        if (r < nrows && gm >= 0 && gm < HY && gn >= 0 && gn < WY)
            v = g_y[(((size_t)n * CH + c) * HY + gm) * WY + gn];
        ys[c][r][col] = v;
    }
    __syncthreads();

    int q = q0 + tx;
    int qodd = q & 1;
    int cl0 = qodd ? (tx - 1) / 2 : tx / 2;

    // upsample weights (x2 per axis folded in; zero-padded to 4 taps)
    float wr[4], wc[4];
    if (odd) { wr[0] = 2.f * P.g7[0]; wr[1] = 2.f * P.g7[2]; wr[2] = 2.f * P.g7[4]; wr[3] = 2.f * P.g7[6]; }
    else     { wr[0] = 2.f * P.g7[1]; wr[1] = 2.f * P.g7[3]; wr[2] = 2.f * P.g7[5]; wr[3] = 0.f; }
    if (qodd) { wc[0] = 2.f * P.g7[0]; wc[1] = 2.f * P.g7[2]; wc[2] = 2.f * P.g7[4]; wc[3] = 2.f * P.g7[6]; }
    else      { wc[0] = 2.f * P.g7[1]; wc[1] = 2.f * P.g7[3]; wc[2] = 2.f * P.g7[5]; wc[3] = 0.f; }

    float xr[CH];
#pragma unroll
    for (int c = 0; c < CH; c++) {
        float acc = 0.f;
#pragma unroll
        for (int i = 0; i < 4; i++) {
            float ra = 0.f;
#pragma unroll
            for (int j = 0; j < 4; j++) ra += wc[j] * ys[c][i][cl0 + j];
            acc += wr[i] * ra;
        }
        xr[c] = acc;
    }

    // GMM responsibilities
    float lg[GMIX];
    float mx = -1e30f;
#pragma unroll
    for (int g = 0; g < GMIX; g++) {
        float d0 = xr[0] - P.mu[g][0];
        float d1 = xr[1] - P.mu[g][1];
        float d2 = xr[2] - P.mu[g][2];
        float quad = d0 * d0 * P.Sinv[g][0] + d1 * d1 * P.Sinv[g][3] + d2 * d2 * P.Sinv[g][5]
                   + 2.f * (d0 * d1 * P.Sinv[g][1] + d0 * d2 * P.Sinv[g][2] + d1 * d2 * P.Sinv[g][4]);
        float l = -0.5f * quad - P.halflogdet[g] + P.logpi[g];
        lg[g] = l;
        mx = fmaxf(mx, l);
    }
    float se = 0.f;
#pragma unroll
    for (int g = 0; g < GMIX; g++) { lg[g] = __expf(lg[g] - mx); se += lg[g]; }
    float sinv = 1.f / se;

    // fuzzy membership per (g, m)
#pragma unroll
    for (int g = 0; g < GMIX; g++) {
        float xg = lg[g] * sinv;
        float z0, z1, z2;
        {
            float cg = P.c[g][0];
            float rs = (xg < cg) ? P.rL[g][0] : P.rR[g][0];
            float t = (xg - cg) * rs;
            z0 = __expf(-0.5f * t * t);
        }
        {
            float cg = P.c[g][1];
            float rs = (xg < cg) ? P.rL[g][1] : P.rR[g][1];
            float t = (xg - cg) * rs;
            z1 = __expf(-0.5f * t * t);
        }
        {
            float cg = P.c[g][2];
            float rs = (xg < cg) ? P.rL[g][2] : P.rR[g][2];
            float t = (xg - cg) * rs;
            z2 = __expf(-0.5f * t * t);
        }
        float zin = 1.f / (z0 + z1 + z2);
        so[tx * 15 + g * 3 + 0] = z0 * zin;
        so[tx * 15 + g * 3 + 1] = z1 * zin;
        so[tx * 15 + g * 3 + 2] = z2 * zin;
    }
    __syncthreads();

    // coalesced write: 1920 contiguous floats per block
    size_t base = (((size_t)n * HH + p) * WW + q0) * (GMIX * MF);
#pragma unroll
    for (int i = 0; i < 15; i++) out[base + tx + i * 128] = so[tx + i * 128];
}

extern "C" void kernel_launch(void* const* d_in, const int* in_sizes, int n_in,
                              void* d_out, int out_size) {
    const float* x     = (const float*)d_in[0];
    const float* mu    = (const float*)d_in[1];
    const float* L_raw = (const float*)d_in[2];
    const float* pi    = (const float*)d_in[3];
    const float* mf_c  = (const float*)d_in[4];
    const float* mf_sL = (const float*)d_in[5];
    const float* mf_sR = (const float*)d_in[6];
    float* out = (float*)d_out;

    precompute_kernel<<<1, 1>>>(mu, L_raw, pi, mf_c, mf_sL, mf_sR);

    dim3 g1(WY / 32, HY / 8, NIMG * CH);
    down_kernel<<<g1, 256>>>(x);

    main_kernel<<<NIMG * 512 * 4, 128>>>(out);
}

// round 2
// speedup vs baseline: 1.4087x; 1.4087x over previous
#include <cuda_runtime.h>
#include <math.h>

#define NIMG 8
#define CH 3
#define HH 512
#define WW 512
#define GMIX 5
#define MF 3
#define HY 256
#define WY 256

// 6.3 MB scratch for downsampled y
__device__ float g_y[NIMG * CH * HY * WY];

struct Params {
    float Sinv[GMIX][6];      // symmetric 3x3: s00,s01,s02,s11,s12,s22
    float halflogdet[GMIX];
    float logpi[GMIX];
    float mu[GMIX][CH];
    float c[GMIX][MF];
    float rL[GMIX][MF];       // 1/sL
    float rR[GMIX][MF];       // 1/sR
};
__device__ Params g_P;

__device__ __forceinline__ double softplus_d(double x) {
    if (x > 30.0) return x;
    return log1p(exp(x));
}

// Parallelized: thread g does the per-Gaussian Sigma chain, thread g*3+m does
// the membership widths, thread 31 does log_softmax(pi).
__global__ void precompute_kernel(const float* __restrict__ mu,
                                  const float* __restrict__ L_raw,
                                  const float* __restrict__ pi,
                                  const float* __restrict__ mf_c,
                                  const float* __restrict__ mf_sL,
                                  const float* __restrict__ mf_sR) {
    int t = threadIdx.x;

    if (t == 31) {
        double mx = -1e30;
        for (int g = 0; g < GMIX; g++) mx = fmax(mx, (double)pi[g]);
        double s = 0.0;
        for (int g = 0; g < GMIX; g++) s += exp((double)pi[g] - mx);
        double lse = mx + log(s);
        for (int g = 0; g < GMIX; g++) g_P.logpi[g] = (float)((double)pi[g] - lse);
    }

    if (t < GMIX * MF) {
        int g = t / MF, m = t - g * MF;
        g_P.c[g][m] = mf_c[g * MF + m];
        double sL = softplus_d((double)mf_sL[g * MF + m]) + 1e-12;
        double sR = softplus_d((double)mf_sR[g * MF + m]) + 1e-12;
        g_P.rL[g][m] = (float)(1.0 / sL);
        g_P.rR[g][m] = (float)(1.0 / sR);
    }

    if (t < GMIX) {
        int g = t;
        for (int i = 0; i < CH; i++) g_P.mu[g][i] = mu[g * CH + i];
        // build L (tril, transformed diagonal)
        double L[3][3];
        for (int i = 0; i < 3; i++)
            for (int j = 0; j < 3; j++) {
                double v = (double)L_raw[(g * 3 + i) * 3 + j];
                L[i][j] = (j < i) ? v : 0.0;
            }
        for (int i = 0; i < 3; i++) {
            double d = softplus_d((double)L_raw[(g * 3 + i) * 3 + i]) + 1e-4;  // MIN_DIAG
            d = softplus_d(d) + 1e-4;                                          // SIG_EPS
            L[i][i] = d;
        }
        // Sigma = L L^T + SIG_EPS I
        double Sg[3][3];
        for (int i = 0; i < 3; i++)
            for (int j = 0; j < 3; j++) {
                double acc = 0.0;
                for (int k = 0; k < 3; k++) acc += L[i][k] * L[j][k];
                Sg[i][j] = acc + (i == j ? 1e-4 : 0.0);
            }
        double det = Sg[0][0] * (Sg[1][1] * Sg[2][2] - Sg[1][2] * Sg[2][1])
                   - Sg[0][1] * (Sg[1][0] * Sg[2][2] - Sg[1][2] * Sg[2][0])
                   + Sg[0][2] * (Sg[1][0] * Sg[2][1] - Sg[1][1] * Sg[2][0]);
        g_P.halflogdet[g] = (float)(0.5 * log(det));
        // A = Sigma + JITTER I ; Sinv = A^{-1} (pinv of SPD = inverse)
        double A[3][3];
        for (int i = 0; i < 3; i++)
            for (int j = 0; j < 3; j++) A[i][j] = Sg[i][j] + (i == j ? 1e-3 : 0.0);
        double dA = A[0][0] * (A[1][1] * A[2][2] - A[1][2] * A[2][1])
                  - A[0][1] * (A[1][0] * A[2][2] - A[1][2] * A[2][0])
                  + A[0][2] * (A[1][0] * A[2][1] - A[1][1] * A[2][0]);
        g_P.Sinv[g][0] = (float)( (A[1][1] * A[2][2] - A[1][2] * A[2][1]) / dA);
        g_P.Sinv[g][1] = (float)(-(A[0][1] * A[2][2] - A[0][2] * A[2][1]) / dA);
        g_P.Sinv[g][2] = (float)( (A[0][1] * A[1][2] - A[0][2] * A[1][1]) / dA);
        g_P.Sinv[g][3] = (float)( (A[0][0] * A[2][2] - A[0][2] * A[2][0]) / dA);
        g_P.Sinv[g][4] = (float)(-(A[0][0] * A[1][2] - A[0][2] * A[1][0]) / dA);
        g_P.Sinv[g][5] = (float)( (A[0][0] * A[1][1] - A[0][1] * A[1][0]) / dA);
    }
}

// ---------------------------------------------------------------------------
// Kernel 1: separable 7x7 gaussian blur, reflect pad, stride 2.
// Tile: 32x8 outputs per block. Taps computed in registers (no param dep).
// ---------------------------------------------------------------------------
__global__ void __launch_bounds__(256) down_kernel(const float* __restrict__ x) {
    __shared__ float xs[21][69];
    __shared__ float tmp[21][32];

    int tx = threadIdx.x & 31;
    int ty = threadIdx.x >> 5;
    int j0 = blockIdx.x * 32;
    int i0 = blockIdx.y * 8;
    int zc = blockIdx.z;  // n*CH + c
    const float* xin = x + (size_t)zc * HH * WW;

    // taps in registers (uniform): g = exp(-r^2/(2*0.81)) normalized
    const float inv2s2 = 1.0f / 1.62f;
    float e1 = expf(-1.0f * inv2s2);
    float e2 = expf(-4.0f * inv2s2);
    float e3 = expf(-9.0f * inv2s2);
    float sinv = 1.0f / (1.0f + 2.0f * (e1 + e2 + e3));
    float gw[7] = { e3 * sinv, e2 * sinv, e1 * sinv, sinv, e1 * sinv, e2 * sinv, e3 * sinv };

    for (int idx = threadIdx.x; idx < 21 * 69; idx += 256) {
        int rr = idx / 69, cc = idx - rr * 69;
        int r = 2 * i0 - 3 + rr;
        int c = 2 * j0 - 3 + cc;
        r = (r < 0) ? -r : (r >= HH ? 2 * HH - 2 - r : r);
        c = (c < 0) ? -c : (c >= WW ? 2 * WW - 2 - c : c);
        xs[rr][cc] = xin[r * WW + c];
    }
    __syncthreads();

    // horizontal pass (stride-2)
    for (int r = ty; r < 21; r += 8) {
        float acc = 0.f;
#pragma unroll
        for (int b = 0; b < 7; b++) acc += gw[b] * xs[r][2 * tx + b];
        tmp[r][tx] = acc;
    }
    __syncthreads();

    // vertical pass (stride-2)
    float acc = 0.f;
#pragma unroll
    for (int a = 0; a < 7; a++) acc += gw[a] * tmp[2 * ty + a][tx];
    g_y[((size_t)zc * HY + (i0 + ty)) * WY + (j0 + tx)] = acc;
}

// ---------------------------------------------------------------------------
// Kernel 2: fused upsample + GMM responsibilities + fuzzy membership.
// One block = 256 consecutive pixels of one row. Vertical upsample taps are
// uniform per block -> precombine rows into rc[c][col] once, then each pixel
// does only a 4-tap horizontal pass. Output staged in smem for coalesced
// stores.
// ---------------------------------------------------------------------------
#define NCOL 131
__global__ void __launch_bounds__(256) main_kernel(float* __restrict__ out) {
    __shared__ float rc[CH][NCOL + 1];
    __shared__ Params P;
    __shared__ float so[256 * GMIX * MF];

    int tx = threadIdx.x;
    int b = blockIdx.x;
    int qb = b & 1;
    int p  = (b >> 1) & 511;
    int n  = b >> 10;
    int q0 = qb * 256;

    // params -> smem
    {
        const float* src = (const float*)&g_P;
        float* dst = (float*)&P;
        const int nP = (int)(sizeof(Params) / 4);
        for (int i = tx; i < nP; i += 256) dst[i] = src[i];
    }

    // taps (uniform, registers): 2*g[k], g = [e3,e2,e1,1,e1,e2,e3]/s
    const float inv2s2 = 1.0f / 1.62f;
    float e1 = expf(-1.0f * inv2s2);
    float e2 = expf(-4.0f * inv2s2);
    float e3 = expf(-9.0f * inv2s2);
    float sr = 2.0f / (1.0f + 2.0f * (e1 + e2 + e3));
    float t0 = e3 * sr, t1 = e2 * sr, t2 = e1 * sr, t3 = sr;

    int odd   = p & 1;
    int m0    = odd ? (p - 3) / 2 : p / 2 - 1;
    int nrows = 3 + odd;
    int n0    = q0 / 2 - 1;

    float wrk[4];
    if (odd) { wrk[0] = t0; wrk[1] = t2; wrk[2] = t2; wrk[3] = t0; }
    else     { wrk[0] = t1; wrk[1] = t3; wrk[2] = t1; wrk[3] = 0.f; }

    // precombine vertical taps: rc[c][col] = sum_i wr[i]*y[m0+i][n0+col]
    for (int idx = tx; idx < CH * NCOL; idx += 256) {
        int c   = idx / NCOL;
        int col = idx - c * NCOL;
        int gn  = n0 + col;
        float acc = 0.f;
        if (gn >= 0 && gn < WY) {
            const float* yp = g_y + ((size_t)n * CH + c) * HY * WY + gn;
#pragma unroll
            for (int i = 0; i < 4; i++) {
                int gm = m0 + i;
                if (i < nrows && gm >= 0 && gm < HY) acc += wrk[i] * yp[(size_t)gm * WY];
            }
        }
        rc[c][col] = acc;
    }
    __syncthreads();

    int qodd = tx & 1;
    int cl0  = qodd ? (tx - 1) / 2 : tx / 2;
    float wc0, wc1, wc2, wc3;
    if (qodd) { wc0 = t0; wc1 = t2; wc2 = t2; wc3 = t0; }
    else      { wc0 = t1; wc1 = t3; wc2 = t1; wc3 = 0.f; }

    float xr[CH];
#pragma unroll
    for (int c = 0; c < CH; c++)
        xr[c] = wc0 * rc[c][cl0] + wc1 * rc[c][cl0 + 1] + wc2 * rc[c][cl0 + 2] + wc3 * rc[c][cl0 + 3];

    // GMM responsibilities
    float lg[GMIX];
    float mx = -1e30f;
#pragma unroll
    for (int g = 0; g < GMIX; g++) {
        float d0 = xr[0] - P.mu[g][0];
        float d1 = xr[1] - P.mu[g][1];
        float d2 = xr[2] - P.mu[g][2];
        float quad = d0 * d0 * P.Sinv[g][0] + d1 * d1 * P.Sinv[g][3] + d2 * d2 * P.Sinv[g][5]
                   + 2.f * (d0 * d1 * P.Sinv[g][1] + d0 * d2 * P.Sinv[g][2] + d1 * d2 * P.Sinv[g][4]);
        float l = -0.5f * quad - P.halflogdet[g] + P.logpi[g];
        lg[g] = l;
        mx = fmaxf(mx, l);
    }
    float se = 0.f;
#pragma unroll
    for (int g = 0; g < GMIX; g++) { lg[g] = __expf(lg[g] - mx); se += lg[g]; }
    float sinv = 1.f / se;

    // fuzzy membership per (g, m)
#pragma unroll
    for (int g = 0; g < GMIX; g++) {
        float xg = lg[g] * sinv;
        float z0, z1, z2;
        {
            float cg = P.c[g][0];
            float rs = (xg < cg) ? P.rL[g][0] : P.rR[g][0];
            float t = (xg - cg) * rs;
            z0 = __expf(-0.5f * t * t);
        }
        {
            float cg = P.c[g][1];
            float rs = (xg < cg) ? P.rL[g][1] : P.rR[g][1];
            float t = (xg - cg) * rs;
            z1 = __expf(-0.5f * t * t);
        }
        {
            float cg = P.c[g][2];
            float rs = (xg < cg) ? P.rL[g][2] : P.rR[g][2];
            float t = (xg - cg) * rs;
            z2 = __expf(-0.5f * t * t);
        }
        float zin = 1.f / (z0 + z1 + z2);
        so[tx * 15 + g * 3 + 0] = z0 * zin;
        so[tx * 15 + g * 3 + 1] = z1 * zin;
        so[tx * 15 + g * 3 + 2] = z2 * zin;
    }
    __syncthreads();

    // coalesced write: 3840 contiguous floats per block
    size_t base = (((size_t)n * HH + p) * WW + q0) * (GMIX * MF);
#pragma unroll
    for (int i = 0; i < 15; i++) out[base + tx + i * 256] = so[tx + i * 256];
}

extern "C" void kernel_launch(void* const* d_in, const int* in_sizes, int n_in,
                              void* d_out, int out_size) {
    const float* x     = (const float*)d_in[0];
    const float* mu    = (const float*)d_in[1];
    const float* L_raw = (const float*)d_in[2];
    const float* pi    = (const float*)d_in[3];
    const float* mf_c  = (const float*)d_in[4];
    const float* mf_sL = (const float*)d_in[5];
    const float* mf_sR = (const float*)d_in[6];
    float* out = (float*)d_out;

    precompute_kernel<<<1, 32>>>(mu, L_raw, pi, mf_c, mf_sL, mf_sR);

    dim3 g1(WY / 32, HY / 8, NIMG * CH);
    down_kernel<<<g1, 256>>>(x);

    main_kernel<<<NIMG * 512 * 2, 256>>>(out);
}